// round 3
// baseline (speedup 1.0000x reference)
#include <cuda_runtime.h>
#include <cuda_bf16.h>

#define N_TOTAL 8700
#define N_YOLO  8400
#define N_WORDS 136          // ceil(8700/64)
#define N_PAD   8704
#define LAST_BITS 60         // 8700 - 135*64

// ---------------- scratch (static device globals; no allocation) ----------------
__device__ float u_x1[N_PAD], u_y1[N_PAD], u_x2[N_PAD], u_y2[N_PAD], u_conf[N_PAD];
__device__ unsigned long long u_key[N_PAD];
__device__ int g_rank[N_PAD];
__device__ float s_x1[N_PAD], s_y1[N_PAD], s_x2[N_PAD], s_y2[N_PAD], s_conf[N_PAD], s_area[N_PAD];
__device__ unsigned long long g_mask[(size_t)N_TOTAL * N_WORDS];   // 9.46 MB, L2-resident
__device__ unsigned long long g_remv[N_WORDS];

// ---------------- K1: concat + clip + cxcywh->xyxy + sort key ----------------
__global__ void k_prep(const float* __restrict__ yb, const float* __restrict__ yc,
                       const float* __restrict__ rb, const float* __restrict__ rc) {
    int i = blockIdx.x * blockDim.x + threadIdx.x;
    if (i >= N_TOTAL) return;
    float cx, cy, w, h, c;
    if (i < N_YOLO) {
        const float* p = yb + 4 * i;
        cx = p[0]; cy = p[1]; w = p[2]; h = p[3];
        c = yc[i];
    } else {
        int k = i - N_YOLO;
        const float* p = rb + 4 * k;
        cx = p[0]; cy = p[1]; w = p[2]; h = p[3];
        c = rc[k];
    }
    c = fminf(fmaxf(c, 0.0f), 1.0f);
    float hw = __fmul_rn(w, 0.5f);
    float hh = __fmul_rn(h, 0.5f);
    u_x1[i] = __fsub_rn(cx, hw);
    u_y1[i] = __fsub_rn(cy, hh);
    u_x2[i] = __fadd_rn(cx, hw);
    u_y2[i] = __fadd_rn(cy, hh);
    u_conf[i] = c;
    // descending conf, ties -> ascending original index (stable argsort semantics)
    u_key[i] = ((unsigned long long)__float_as_uint(c) << 32)
             | (unsigned long long)(0xFFFFFFFFu - (unsigned)i);
    g_rank[i] = 0;
}

// ---------------- K2: rank = #{j : key[j] > key[i]} (split over j-chunks) ----------------
#define CHUNK 2176
__global__ void k_rank() {
    __shared__ unsigned long long sk[CHUNK];
    int jbase = blockIdx.y * CHUNK;
    for (int t = threadIdx.x; t < CHUNK; t += blockDim.x) {
        int j = jbase + t;
        sk[t] = (j < N_TOTAL) ? u_key[j] : 0ull;   // 0 never beats a real key
    }
    __syncthreads();
    int i = blockIdx.x * blockDim.x + threadIdx.x;
    if (i >= N_TOTAL) return;
    unsigned long long ki = u_key[i];
    int cnt = 0;
#pragma unroll 8
    for (int t = 0; t < CHUNK; t++)
        cnt += (sk[t] > ki) ? 1 : 0;
    atomicAdd(&g_rank[i], cnt);
}

// ---------------- K3: scatter into sorted order + precompute area ----------------
__global__ void k_scatter() {
    int i = blockIdx.x * blockDim.x + threadIdx.x;
    if (i >= N_TOTAL) return;
    int r = g_rank[i];
    float x1 = u_x1[i], y1 = u_y1[i], x2 = u_x2[i], y2 = u_y2[i];
    s_x1[r] = x1; s_y1[r] = y1; s_x2[r] = x2; s_y2[r] = y2;
    s_conf[r] = u_conf[i];
    s_area[r] = __fmul_rn(__fsub_rn(x2, x1), __fsub_rn(y2, y1));
}

// ---------------- K4: suppression bitmask (row i suppresses j>i with iou>0.5) ----------------
#define IT 32   // i rows per block
#define WT 8    // mask words per block (8*64 = 512 j's)
__global__ void k_mask() {
    __shared__ float jx1[WT * 64], jy1[WT * 64], jx2[WT * 64], jy2[WT * 64], ja[WT * 64];
    int i0 = blockIdx.x * IT;
    int w0 = blockIdx.y * WT;
    int jb0 = w0 * 64;
    for (int t = threadIdx.x; t < WT * 64; t += blockDim.x) {
        int j = jb0 + t;
        bool v = (j < N_TOTAL);
        jx1[t] = v ? s_x1[j] : 0.0f;
        jy1[t] = v ? s_y1[j] : 0.0f;
        jx2[t] = v ? s_x2[j] : 0.0f;
        jy2[t] = v ? s_y2[j] : 0.0f;
        ja[t]  = v ? s_area[j] : 0.0f;
    }
    __syncthreads();
    int il = threadIdx.x & 31;
    int wl = threadIdx.x >> 5;
    int i = i0 + il;
    if (i >= N_TOTAL) return;
    int word = w0 + wl;
    int jbase = word * 64;
    unsigned long long bits = 0ull;
    if (jbase + 63 > i) {   // otherwise entire word is below/at diagonal -> zero
        float x1 = s_x1[i], y1 = s_y1[i], x2 = s_x2[i], y2 = s_y2[i], ai = s_area[i];
        int tb = wl * 64;
#pragma unroll 8
        for (int b = 0; b < 64; b++) {
            int j = jbase + b;
            if (j > i && j < N_TOTAL) {
                float iw = fmaxf(__fsub_rn(fminf(x2, jx2[tb + b]), fmaxf(x1, jx1[tb + b])), 0.0f);
                float ih = fmaxf(__fsub_rn(fminf(y2, jy2[tb + b]), fmaxf(y1, jy1[tb + b])), 0.0f);
                float inter = __fmul_rn(iw, ih);
                float uni = __fsub_rn(__fadd_rn(ai, ja[tb + b]), inter);
                // safe pre-filter: if inter <= 0.49*uni then iou < 0.5 guaranteed.
                if (inter > __fmul_rn(0.49f, uni)) {
                    float iou = __fdiv_rn(inter, fmaxf(uni, 1e-9f));
                    if (iou > 0.5f) bits |= (1ull << b);
                }
            }
        }
    }
    g_mask[(size_t)i * N_WORDS + word] = bits;
}

// ---------------- K5: single-block serial bitmask scan (greedy NMS) ----------------
__global__ void k_scan() {
    __shared__ unsigned long long remv[N_WORDS];
    __shared__ unsigned long long diag[2][64];
    __shared__ int s_list[64];
    __shared__ int s_cnt;
    int tid = threadIdx.x;
    if (tid < N_WORDS) remv[tid] = 0ull;
    if (tid < 64) {
        int e = tid;
        diag[0][tid] = (e < N_TOTAL) ? g_mask[(size_t)e * N_WORDS + 0] : 0ull;
    }
    __syncthreads();
    int cur = 0;
    for (int g = 0; g < N_WORDS; g++) {
        if (tid == 0) {
            unsigned long long removed = remv[g];
            unsigned long long valid = (g == N_WORDS - 1) ? ((1ull << LAST_BITS) - 1ull)
                                                          : ~0ull;
            unsigned long long alive = ~removed & valid;
            int cnt = 0;
            while (alive) {
                int b = __ffsll(alive) - 1;
                s_list[cnt++] = b;
                removed |= diag[cur][b];
                alive &= ~(removed | (1ull << b));
            }
            remv[g] = removed;        // in-group suppressions included via diag rows
            s_cnt = cnt;
        }
        // prefetch next group's diagonal words (independent of the resolve)
        if (tid >= 64 && tid < 128 && g + 1 < N_WORDS) {
            int e = (g + 1) * 64 + (tid - 64);
            diag[cur ^ 1][tid - 64] = (e < N_TOTAL)
                ? g_mask[(size_t)e * N_WORDS + (g + 1)] : 0ull;
        }
        __syncthreads();
        int cnt = s_cnt;
        if (tid < N_WORDS && tid > g) {
            unsigned long long r = remv[tid];
            size_t rowbase = (size_t)(g * 64) * N_WORDS + tid;
            for (int k = 0; k < cnt; k++) {
                r |= g_mask[rowbase + (size_t)s_list[k] * N_WORDS];
            }
            remv[tid] = r;
        }
        cur ^= 1;
        __syncthreads();
    }
    if (tid < N_WORDS) g_remv[tid] = remv[tid];
}

// ---------------- K6: write (x1,y1,x2,y2,conf) * keep ----------------
__global__ void k_out(float* __restrict__ out) {
    int r = blockIdx.x * blockDim.x + threadIdx.x;
    if (r >= N_TOTAL) return;
    bool keep = !((g_remv[r >> 6] >> (r & 63)) & 1ull);
    float m = keep ? 1.0f : 0.0f;
    out[r * 5 + 0] = __fmul_rn(s_x1[r], m);
    out[r * 5 + 1] = __fmul_rn(s_y1[r], m);
    out[r * 5 + 2] = __fmul_rn(s_x2[r], m);
    out[r * 5 + 3] = __fmul_rn(s_y2[r], m);
    out[r * 5 + 4] = __fmul_rn(s_conf[r], m);
}

// ---------------- launch ----------------
extern "C" void kernel_launch(void* const* d_in, const int* in_sizes, int n_in,
                              void* d_out, int out_size) {
    const float* yb = (const float*)d_in[0];   // yolo_cxcywh   [8400,4]
    const float* yc = (const float*)d_in[1];   // yolo_conf     [8400]
    const float* rb = (const float*)d_in[2];   // rtdetr_cxcywh [300,4]
    const float* rc = (const float*)d_in[3];   // rtdetr_conf   [300]
    float* out = (float*)d_out;

    const int TB = 256;
    const int NB = (N_TOTAL + TB - 1) / TB;    // 34

    k_prep<<<NB, TB>>>(yb, yc, rb, rc);
    k_rank<<<dim3(NB, (N_TOTAL + CHUNK - 1) / CHUNK), TB>>>();
    k_scatter<<<NB, TB>>>();
    k_mask<<<dim3((N_TOTAL + IT - 1) / IT, N_WORDS / WT), 256>>>();
    k_scan<<<1, 256>>>();
    k_out<<<NB, TB>>>(out);
}

// round 4
// speedup vs baseline: 1.9085x; 1.9085x over previous
#include <cuda_runtime.h>
#include <cuda_bf16.h>

#define N_TOTAL 8700
#define N_YOLO  8400
#define N_WORDS 136          // ceil(8700/64)
#define N_PAD   8704
#define LAST_BITS 60         // 8700 - 135*64

// ---------------- scratch (static device globals; no allocation) ----------------
__device__ float u_x1[N_PAD], u_y1[N_PAD], u_x2[N_PAD], u_y2[N_PAD], u_conf[N_PAD];
__device__ unsigned long long u_key[N_PAD];
__device__ int g_rank[N_PAD];
// s_* pads [8700..8703] stay zero-initialized: box (0,0,0,0) yields inter=0 -> never suppresses.
__device__ float s_x1[N_PAD], s_y1[N_PAD], s_x2[N_PAD], s_y2[N_PAD], s_conf[N_PAD];
__device__ unsigned long long g_mask[(size_t)N_TOTAL * N_WORDS];   // 9.46 MB, L2-resident
__device__ unsigned long long g_remv[N_WORDS];

// ---------------- K1: concat + clip + cxcywh->xyxy + sort key ----------------
__global__ void k_prep(const float* __restrict__ yb, const float* __restrict__ yc,
                       const float* __restrict__ rb, const float* __restrict__ rc) {
    int i = blockIdx.x * blockDim.x + threadIdx.x;
    if (i >= N_TOTAL) return;
    float cx, cy, w, h, c;
    if (i < N_YOLO) {
        const float* p = yb + 4 * i;
        cx = p[0]; cy = p[1]; w = p[2]; h = p[3];
        c = yc[i];
    } else {
        int k = i - N_YOLO;
        const float* p = rb + 4 * k;
        cx = p[0]; cy = p[1]; w = p[2]; h = p[3];
        c = rc[k];
    }
    c = fminf(fmaxf(c, 0.0f), 1.0f);
    float hw = __fmul_rn(w, 0.5f);
    float hh = __fmul_rn(h, 0.5f);
    u_x1[i] = __fsub_rn(cx, hw);
    u_y1[i] = __fsub_rn(cy, hh);
    u_x2[i] = __fadd_rn(cx, hw);
    u_y2[i] = __fadd_rn(cy, hh);
    u_conf[i] = c;
    // descending conf, ties -> ascending original index (stable argsort semantics)
    u_key[i] = ((unsigned long long)__float_as_uint(c) << 32)
             | (unsigned long long)(0xFFFFFFFFu - (unsigned)i);
    g_rank[i] = 0;
}

// ---------------- K2: rank = #{j : key[j] > key[i]} (split over j-chunks) ----------------
#define CHUNK 2176
__global__ void k_rank() {
    __shared__ unsigned long long sk[CHUNK];
    int jbase = blockIdx.y * CHUNK;
    for (int t = threadIdx.x; t < CHUNK; t += blockDim.x) {
        int j = jbase + t;
        sk[t] = (j < N_TOTAL) ? u_key[j] : 0ull;   // 0 never beats a real key
    }
    __syncthreads();
    int i = blockIdx.x * blockDim.x + threadIdx.x;
    if (i >= N_TOTAL) return;
    unsigned long long ki = u_key[i];
    int cnt = 0;
#pragma unroll 8
    for (int t = 0; t < CHUNK; t++)
        cnt += (sk[t] > ki) ? 1 : 0;
    atomicAdd(&g_rank[i], cnt);
}

// ---------------- K3: scatter into sorted order ----------------
__global__ void k_scatter() {
    int i = blockIdx.x * blockDim.x + threadIdx.x;
    if (i >= N_TOTAL) return;
    int r = g_rank[i];
    s_x1[r] = u_x1[i]; s_y1[r] = u_y1[i];
    s_x2[r] = u_x2[i]; s_y2[r] = u_y2[i];
    s_conf[r] = u_conf[i];
}

// ---------------- K4: suppression bitmask (row i suppresses j>i with iou>0.5) ----------------
#define IT 32   // i rows per block
#define WT 8    // mask words per block (8*64 = 512 j's)
__global__ void k_mask() {
    __shared__ float4 jb[WT * 64];
    int i0 = blockIdx.x * IT;
    int w0 = blockIdx.y * WT;
    int jb0 = w0 * 64;
    if (jb0 + WT * 64 <= i0) return;          // block fully below diagonal: never read
    for (int t = threadIdx.x; t < WT * 64; t += blockDim.x) {
        int j = jb0 + t;                      // j <= 8703 < N_PAD always
        jb[t] = make_float4(s_x1[j], s_y1[j], s_x2[j], s_y2[j]);
    }
    __syncthreads();
    int il = threadIdx.x & 31;
    int wl = threadIdx.x >> 5;
    int i = i0 + il;
    if (i >= N_TOTAL) return;
    int word = w0 + wl;
    int jbase = word * 64;
    float x1 = s_x1[i], y1 = s_y1[i], x2 = s_x2[i], y2 = s_y2[i];
    float ai = __fmul_rn(__fsub_rn(x2, x1), __fsub_rn(y2, y1));
    unsigned long long bits = 0ull;
    int tb = wl * 64;
#pragma unroll 16
    for (int b = 0; b < 64; b++) {
        float4 J = jb[tb + b];
        float iw = fmaxf(__fsub_rn(fminf(x2, J.z), fmaxf(x1, J.x)), 0.0f);
        float ih = fmaxf(__fsub_rn(fminf(y2, J.w), fmaxf(y1, J.y)), 0.0f);
        float inter = __fmul_rn(iw, ih);
        float aj = __fmul_rn(__fsub_rn(J.z, J.x), __fsub_rn(J.w, J.y));
        float uni = __fsub_rn(__fadd_rn(ai, aj), inter);
        // safe pre-filter: inter <= 0.49*uni guarantees iou < 0.5 (division skipped)
        if (inter > __fmul_rn(0.49f, uni)) {
            if (__fdiv_rn(inter, fmaxf(uni, 1e-9f)) > 0.5f) bits |= (1ull << b);
        }
    }
    if (jbase <= i) {                         // straddling / below word: mask j<=i bits
        int d = i - jbase;
        bits = (d >= 63) ? 0ull : (bits & (~0ull << (d + 1)));
    }
    g_mask[(size_t)i * N_WORDS + word] = bits;
}

// ---------------- K5: single-block pipelined bitmask scan (greedy NMS) ----------------
// Phase A: warp 1 urgently ORs prev-group accepted rows into column g.
// Phase B (concurrent): t0 resolves group g (depth-4 speculative diag loads);
//   warps 2-3 prefetch diag(g+1); warps 4+ bulk-apply prev list to columns >g (4 thr/col).
__global__ void k_scan() {
    __shared__ unsigned long long remv[N_WORDS];
    __shared__ unsigned long long diag[2][64];
    __shared__ int s_list[2][64];
    __shared__ int s_cnt[2];
    int tid = threadIdx.x;
    if (tid < N_WORDS) remv[tid] = 0ull;
    if (tid >= 64 && tid < 128)
        diag[0][tid - 64] = g_mask[(size_t)(tid - 64) * N_WORDS + 0];
    if (tid == 0) { s_cnt[0] = 0; s_cnt[1] = 0; }
    __syncthreads();

    for (int g = 0; g < N_WORDS; g++) {
        int cb = g & 1;        // current buffers (diag/list for group g)
        int pb = cb ^ 1;       // prev list buffers (group g-1)
        int pcnt = s_cnt[pb];

        // ---- PHASE A: urgent apply prev list to column g (warp 1) ----
        if (g > 0 && (tid >> 5) == 1 && pcnt > 0) {
            int l = tid & 31;
            size_t base = (size_t)((g - 1) * 64) * N_WORDS + g;
            unsigned long long part = 0ull;
            if (l < pcnt)      part  = g_mask[base + (size_t)s_list[pb][l] * N_WORDS];
            if (l + 32 < pcnt) part |= g_mask[base + (size_t)s_list[pb][l + 32] * N_WORDS];
            unsigned lo = __reduce_or_sync(0xFFFFFFFFu, (unsigned)part);
            unsigned hi = __reduce_or_sync(0xFFFFFFFFu, (unsigned)(part >> 32));
            if (l == 0) remv[g] |= ((unsigned long long)hi << 32) | lo;
        }
        __syncthreads();

        // ---- PHASE B ----
        if (tid == 0) {
            unsigned long long removed = remv[g];
            unsigned long long valid = (g == N_WORDS - 1) ? ((1ull << LAST_BITS) - 1ull)
                                                          : ~0ull;
            unsigned long long acc = 0ull;
            int cnt = 0;
            unsigned long long alive = valid & ~removed;
            while (alive) {
                unsigned long long a = alive;
                int b0 = __ffsll(a) - 1; a &= a - 1;
                int b1 = -1, b2 = -1, b3 = -1;
                if (a) { b1 = __ffsll(a) - 1; a &= a - 1; }
                if (a) { b2 = __ffsll(a) - 1; a &= a - 1; }
                if (a) { b3 = __ffsll(a) - 1; }
                // 4 independent LDS issued together (speculative for b1..b3)
                unsigned long long d0 = diag[cb][b0];
                unsigned long long d1 = (b1 >= 0) ? diag[cb][b1] : 0ull;
                unsigned long long d2 = (b2 >= 0) ? diag[cb][b2] : 0ull;
                unsigned long long d3 = (b3 >= 0) ? diag[cb][b3] : 0ull;
                removed |= d0; acc |= 1ull << b0; s_list[cb][cnt++] = b0;
                if (b1 >= 0 && !((removed >> b1) & 1ull)) {
                    removed |= d1; acc |= 1ull << b1; s_list[cb][cnt++] = b1;
                }
                if (b2 >= 0 && !((removed >> b2) & 1ull)) {
                    removed |= d2; acc |= 1ull << b2; s_list[cb][cnt++] = b2;
                }
                if (b3 >= 0 && !((removed >> b3) & 1ull)) {
                    removed |= d3; acc |= 1ull << b3; s_list[cb][cnt++] = b3;
                }
                alive = valid & ~removed & ~acc;
            }
            remv[g] = removed;
            s_cnt[cb] = cnt;
        } else if (tid >= 64 && tid < 128) {
            if (g + 1 < N_WORDS) {
                int e = (g + 1) * 64 + (tid - 64);
                diag[cb ^ 1][tid - 64] = (e < N_TOTAL)
                    ? g_mask[(size_t)e * N_WORDS + (g + 1)] : 0ull;
            }
        } else if (tid >= 128) {
            int t = tid - 128;
            int col = g + 1 + (t >> 2);
            int p = t & 3;
            if (col < N_WORDS && pcnt > 0) {
                size_t base = (size_t)((g - 1) * 64) * N_WORDS + col;
                unsigned long long a0 = 0, a1 = 0, a2 = 0, a3 = 0;
                int k = p;
                for (; k + 12 < pcnt; k += 16) {   // 4 independent loads in flight
                    a0 |= g_mask[base + (size_t)s_list[pb][k]      * N_WORDS];
                    a1 |= g_mask[base + (size_t)s_list[pb][k + 4]  * N_WORDS];
                    a2 |= g_mask[base + (size_t)s_list[pb][k + 8]  * N_WORDS];
                    a3 |= g_mask[base + (size_t)s_list[pb][k + 12] * N_WORDS];
                }
                for (; k < pcnt; k += 4)
                    a0 |= g_mask[base + (size_t)s_list[pb][k] * N_WORDS];
                unsigned long long part = (a0 | a1) | (a2 | a3);
                if (part) atomicOr(&remv[col], part);
            }
        }
        __syncthreads();
    }
    if (tid < N_WORDS) g_remv[tid] = remv[tid];
}

// ---------------- K6: write (x1,y1,x2,y2,conf) * keep ----------------
__global__ void k_out(float* __restrict__ out) {
    int r = blockIdx.x * blockDim.x + threadIdx.x;
    if (r >= N_TOTAL) return;
    bool keep = !((g_remv[r >> 6] >> (r & 63)) & 1ull);
    float m = keep ? 1.0f : 0.0f;
    out[r * 5 + 0] = __fmul_rn(s_x1[r], m);
    out[r * 5 + 1] = __fmul_rn(s_y1[r], m);
    out[r * 5 + 2] = __fmul_rn(s_x2[r], m);
    out[r * 5 + 3] = __fmul_rn(s_y2[r], m);
    out[r * 5 + 4] = __fmul_rn(s_conf[r], m);
}

// ---------------- launch ----------------
extern "C" void kernel_launch(void* const* d_in, const int* in_sizes, int n_in,
                              void* d_out, int out_size) {
    const float* yb = (const float*)d_in[0];   // yolo_cxcywh   [8400,4]
    const float* yc = (const float*)d_in[1];   // yolo_conf     [8400]
    const float* rb = (const float*)d_in[2];   // rtdetr_cxcywh [300,4]
    const float* rc = (const float*)d_in[3];   // rtdetr_conf   [300]
    float* out = (float*)d_out;

    const int TB = 256;
    const int NB = (N_TOTAL + TB - 1) / TB;    // 34

    k_prep<<<NB, TB>>>(yb, yc, rb, rc);
    k_rank<<<dim3(NB, (N_TOTAL + CHUNK - 1) / CHUNK), TB>>>();
    k_scatter<<<NB, TB>>>();
    k_mask<<<dim3((N_TOTAL + IT - 1) / IT, N_WORDS / WT), 256>>>();
    k_scan<<<1, 1024>>>();
    k_out<<<NB, TB>>>(out);
}

// round 5
// speedup vs baseline: 5.5076x; 2.8859x over previous
#include <cuda_runtime.h>
#include <cuda_bf16.h>

#define N_TOTAL 8700
#define N_YOLO  8400
#define N_WORDS 136          // ceil(8700/64)
#define N_PAD   8704
#define LAST_BITS 60         // 8700 - 135*64
#define CAP     8192         // per-column sparse entry capacity (~100x expected)

// ---------------- scratch (static device globals; no allocation) ----------------
__device__ float u_x1[N_PAD], u_y1[N_PAD], u_x2[N_PAD], u_y2[N_PAD], u_conf[N_PAD];
__device__ unsigned long long u_key[N_PAD];
__device__ int g_rank[N_PAD];
// s_* pads [8700..8703] stay zero: box (0,0,0,0) yields inter=0 -> never suppresses.
__device__ float s_x1[N_PAD], s_y1[N_PAD], s_x2[N_PAD], s_y2[N_PAD], s_conf[N_PAD];
// sparse suppression structure
__device__ int col_count[N_WORDS];                     // zeroed each call in k_prep
__device__ ulonglong2 col_ent[N_WORDS][CAP];           // .x = row index i, .y = 64-bit word
__device__ unsigned long long g_diag[N_PAD];           // in-group suppression word of box i
__device__ unsigned long long g_hasdiag[N_WORDS];      // zeroed each call in k_prep
__device__ unsigned long long g_remv[N_WORDS];

// ---------------- K1: concat + clip + cxcywh->xyxy + sort key + scratch init ----------------
__global__ void k_prep(const float* __restrict__ yb, const float* __restrict__ yc,
                       const float* __restrict__ rb, const float* __restrict__ rc) {
    int i = blockIdx.x * blockDim.x + threadIdx.x;
    if (i < N_WORDS) { col_count[i] = 0; g_hasdiag[i] = 0ull; }
    if (i >= N_TOTAL) return;
    float cx, cy, w, h, c;
    if (i < N_YOLO) {
        const float* p = yb + 4 * i;
        cx = p[0]; cy = p[1]; w = p[2]; h = p[3];
        c = yc[i];
    } else {
        int k = i - N_YOLO;
        const float* p = rb + 4 * k;
        cx = p[0]; cy = p[1]; w = p[2]; h = p[3];
        c = rc[k];
    }
    c = fminf(fmaxf(c, 0.0f), 1.0f);
    float hw = __fmul_rn(w, 0.5f);
    float hh = __fmul_rn(h, 0.5f);
    u_x1[i] = __fsub_rn(cx, hw);
    u_y1[i] = __fsub_rn(cy, hh);
    u_x2[i] = __fadd_rn(cx, hw);
    u_y2[i] = __fadd_rn(cy, hh);
    u_conf[i] = c;
    // descending conf, ties -> ascending original index (stable argsort semantics)
    u_key[i] = ((unsigned long long)__float_as_uint(c) << 32)
             | (unsigned long long)(0xFFFFFFFFu - (unsigned)i);
    g_rank[i] = 0;
}

// ---------------- K2: rank = #{j : key[j] > key[i]} (split over j-chunks) ----------------
#define CHUNK 2176
__global__ void k_rank() {
    __shared__ unsigned long long sk[CHUNK];
    int jbase = blockIdx.y * CHUNK;
    for (int t = threadIdx.x; t < CHUNK; t += blockDim.x) {
        int j = jbase + t;
        sk[t] = (j < N_TOTAL) ? u_key[j] : 0ull;   // 0 never beats a real key
    }
    __syncthreads();
    int i = blockIdx.x * blockDim.x + threadIdx.x;
    if (i >= N_TOTAL) return;
    unsigned long long ki = u_key[i];
    int c0 = 0, c1 = 0;
#pragma unroll 16
    for (int t = 0; t < CHUNK; t += 2) {
        c0 += (sk[t]     > ki) ? 1 : 0;
        c1 += (sk[t + 1] > ki) ? 1 : 0;
    }
    atomicAdd(&g_rank[i], c0 + c1);
}

// ---------------- K3: scatter into sorted order ----------------
__global__ void k_scatter() {
    int i = blockIdx.x * blockDim.x + threadIdx.x;
    if (i >= N_TOTAL) return;
    int r = g_rank[i];
    s_x1[r] = u_x1[i]; s_y1[r] = u_y1[i];
    s_x2[r] = u_x2[i]; s_y2[r] = u_y2[i];
    s_conf[r] = u_conf[i];
}

// ---------------- K4: sparse suppression build (i suppresses j>i with iou>0.5) ----------------
#define IT 32   // i rows per block
#define WT 8    // mask words per block (8*64 = 512 j's)
__global__ void k_mask() {
    __shared__ float4 jb[WT * 64];
    int i0 = blockIdx.x * IT;
    int w0 = blockIdx.y * WT;
    int jb0 = w0 * 64;
    if (jb0 + WT * 64 <= i0) return;          // block fully below diagonal
    for (int t = threadIdx.x; t < WT * 64; t += blockDim.x) {
        int j = jb0 + t;                      // j <= 8703 < N_PAD always
        jb[t] = make_float4(s_x1[j], s_y1[j], s_x2[j], s_y2[j]);
    }
    __syncthreads();
    int il = threadIdx.x & 31;
    int wl = threadIdx.x >> 5;
    int i = i0 + il;
    if (i >= N_TOTAL) return;
    int word = w0 + wl;
    int jbase = word * 64;
    float x1 = s_x1[i], y1 = s_y1[i], x2 = s_x2[i], y2 = s_y2[i];
    float ai = __fmul_rn(__fsub_rn(x2, x1), __fsub_rn(y2, y1));
    unsigned long long bits = 0ull;
    int tb = wl * 64;
#pragma unroll 16
    for (int b = 0; b < 64; b++) {
        float4 J = jb[tb + b];
        float iw = fmaxf(__fsub_rn(fminf(x2, J.z), fmaxf(x1, J.x)), 0.0f);
        float ih = fmaxf(__fsub_rn(fminf(y2, J.w), fmaxf(y1, J.y)), 0.0f);
        float inter = __fmul_rn(iw, ih);
        float aj = __fmul_rn(__fsub_rn(J.z, J.x), __fsub_rn(J.w, J.y));
        float uni = __fsub_rn(__fadd_rn(ai, aj), inter);
        // safe pre-filter: inter <= 0.49*uni guarantees iou < 0.5 (division skipped)
        if (inter > __fmul_rn(0.49f, uni)) {
            if (__fdiv_rn(inter, fmaxf(uni, 1e-9f)) > 0.5f) bits |= (1ull << b);
        }
    }
    int igroup = i >> 6;
    if (word == igroup) {                     // straddling word: mask j<=i, keep as diag
        int d = i - jbase;
        bits = (d >= 63) ? 0ull : (bits & (~0ull << (d + 1)));
        g_diag[i] = bits;
        if (bits) atomicOr(&g_hasdiag[igroup], 1ull << (i & 63));
    } else if (word > igroup && bits) {       // sparse off-diagonal entry
        int pos = atomicAdd(&col_count[word], 1);
        if (pos < CAP) col_ent[word][pos] = make_ulonglong2((unsigned long long)i, bits);
    }
    // word < igroup: all j<=i, nothing to record
}

// ---------------- K5: sparse single-block greedy NMS scan ----------------
// Per group g: (1) parallel OR of keep-gated column entries into s_remv,
//              (2) t0 resolves rare in-group suppressions via g_diag.
__global__ void k_scan() {
    __shared__ unsigned long long keep[N_WORDS];
    __shared__ unsigned long long hds[N_WORDS];
    __shared__ unsigned long long remv_out[N_WORDS];
    __shared__ int scnt[N_WORDS];
    __shared__ unsigned long long s_remv;
    int tid = threadIdx.x;
    if (tid < N_WORDS) {
        hds[tid] = g_hasdiag[tid];
        int c = col_count[tid];
        scnt[tid] = (c > CAP) ? CAP : c;
    }
    if (tid == 0) s_remv = 0ull;
    __syncthreads();

    for (int g = 0; g < N_WORDS; g++) {
        unsigned long long valid = (g == N_WORDS - 1) ? ((1ull << LAST_BITS) - 1ull)
                                                      : ~0ull;
        // t0: speculatively preload up to 4 in-group diag words (overlaps phase-1 latency)
        unsigned long long pre_d0 = 0, pre_d1 = 0, pre_d2 = 0, pre_d3 = 0;
        int pre_b0 = -1, pre_b1 = -1, pre_b2 = -1, pre_b3 = -1;
        unsigned long long hd = 0ull;
        if (tid == 0) {
            hd = hds[g] & valid;
            unsigned long long t = hd;
            if (t) { pre_b0 = __ffsll(t) - 1; t &= t - 1; pre_d0 = g_diag[g * 64 + pre_b0]; }
            if (t) { pre_b1 = __ffsll(t) - 1; t &= t - 1; pre_d1 = g_diag[g * 64 + pre_b1]; }
            if (t) { pre_b2 = __ffsll(t) - 1; t &= t - 1; pre_d2 = g_diag[g * 64 + pre_b2]; }
            if (t) { pre_b3 = __ffsll(t) - 1;             pre_d3 = g_diag[g * 64 + pre_b3]; }
        }
        // phase 1: OR all entries whose source box is kept
        int cnt = scnt[g];
        unsigned long long part = 0ull;
        for (int k = tid; k < cnt; k += blockDim.x) {
            ulonglong2 e = col_ent[g][k];
            int i = (int)e.x;
            if ((keep[i >> 6] >> (i & 63)) & 1ull) part |= e.y;
        }
        unsigned lo = __reduce_or_sync(0xFFFFFFFFu, (unsigned)part);
        unsigned hi = __reduce_or_sync(0xFFFFFFFFu, (unsigned)(part >> 32));
        if ((tid & 31) == 0) {
            unsigned long long w = ((unsigned long long)hi << 32) | lo;
            if (w) atomicOr(&s_remv, w);
        }
        __syncthreads();
        // phase 2: t0 resolves in-group chain (fast path: hd==0 -> no loop)
        if (tid == 0) {
            unsigned long long removed = s_remv;
            s_remv = 0ull;                     // reset for next group (pre-barrier)
            unsigned long long m = hd & ~removed;
            while (m) {
                int b = __ffsll(m) - 1;
                if (!((removed >> b) & 1ull)) {
                    unsigned long long d;
                    if      (b == pre_b0) d = pre_d0;
                    else if (b == pre_b1) d = pre_d1;
                    else if (b == pre_b2) d = pre_d2;
                    else if (b == pre_b3) d = pre_d3;
                    else                  d = g_diag[g * 64 + b];
                    removed |= d;
                }
                m &= m - 1;
                m &= ~removed;
            }
            keep[g] = valid & ~removed;
            remv_out[g] = removed;
        }
        __syncthreads();
    }
    if (tid < N_WORDS) g_remv[tid] = remv_out[tid];
}

// ---------------- K6: write (x1,y1,x2,y2,conf) * keep ----------------
__global__ void k_out(float* __restrict__ out) {
    int r = blockIdx.x * blockDim.x + threadIdx.x;
    if (r >= N_TOTAL) return;
    bool keep = !((g_remv[r >> 6] >> (r & 63)) & 1ull);
    float m = keep ? 1.0f : 0.0f;
    out[r * 5 + 0] = __fmul_rn(s_x1[r], m);
    out[r * 5 + 1] = __fmul_rn(s_y1[r], m);
    out[r * 5 + 2] = __fmul_rn(s_x2[r], m);
    out[r * 5 + 3] = __fmul_rn(s_y2[r], m);
    out[r * 5 + 4] = __fmul_rn(s_conf[r], m);
}

// ---------------- launch ----------------
extern "C" void kernel_launch(void* const* d_in, const int* in_sizes, int n_in,
                              void* d_out, int out_size) {
    const float* yb = (const float*)d_in[0];   // yolo_cxcywh   [8400,4]
    const float* yc = (const float*)d_in[1];   // yolo_conf     [8400]
    const float* rb = (const float*)d_in[2];   // rtdetr_cxcywh [300,4]
    const float* rc = (const float*)d_in[3];   // rtdetr_conf   [300]
    float* out = (float*)d_out;

    const int TB = 256;
    const int NB = (N_TOTAL + TB - 1) / TB;    // 34

    k_prep<<<NB, TB>>>(yb, yc, rb, rc);
    k_rank<<<dim3(NB, (N_TOTAL + CHUNK - 1) / CHUNK), TB>>>();
    k_scatter<<<NB, TB>>>();
    k_mask<<<dim3((N_TOTAL + IT - 1) / IT, N_WORDS / WT), 256>>>();
    k_scan<<<1, 256>>>();
    k_out<<<NB, TB>>>(out);
}

// round 6
// speedup vs baseline: 5.7552x; 1.0450x over previous
#include <cuda_runtime.h>
#include <cuda_bf16.h>

#define N_TOTAL 8700
#define N_YOLO  8400
#define N_WORDS 136          // ceil(8700/64)
#define N_PAD   8704
#define LAST_BITS 60         // 8700 - 135*64
#define CAP     8192         // per-column sparse entry capacity (safety bound)
#define MPT     4            // scan: max register-resident entries per thread (1024/col)

// ---------------- scratch (static device globals; no allocation) ----------------
__device__ float u_x1[N_PAD], u_y1[N_PAD], u_x2[N_PAD], u_y2[N_PAD], u_conf[N_PAD];
__device__ unsigned long long u_key[N_PAD];
__device__ int g_rank[N_PAD];
// s_* pads [8700..8703] stay zero: box (0,0,0,0) yields inter=0 -> never suppresses.
__device__ float s_x1[N_PAD], s_y1[N_PAD], s_x2[N_PAD], s_y2[N_PAD], s_conf[N_PAD];
// sparse suppression structure
__device__ int col_count[N_WORDS];                     // zeroed each call in k_prep
__device__ ulonglong2 col_ent[N_WORDS][CAP];           // .x = row index i, .y = 64-bit word
__device__ unsigned long long g_diag[N_PAD];           // in-group suppression word of box i
__device__ unsigned long long g_hasdiag[N_WORDS];      // zeroed each call in k_prep
__device__ unsigned long long g_remv[N_WORDS];

// ---------------- K1: concat + clip + cxcywh->xyxy + sort key + scratch init ----------------
__global__ void k_prep(const float* __restrict__ yb, const float* __restrict__ yc,
                       const float* __restrict__ rb, const float* __restrict__ rc) {
    int i = blockIdx.x * blockDim.x + threadIdx.x;
    if (i < N_WORDS) { col_count[i] = 0; g_hasdiag[i] = 0ull; }
    if (i >= N_TOTAL) return;
    float cx, cy, w, h, c;
    if (i < N_YOLO) {
        const float* p = yb + 4 * i;
        cx = p[0]; cy = p[1]; w = p[2]; h = p[3];
        c = yc[i];
    } else {
        int k = i - N_YOLO;
        const float* p = rb + 4 * k;
        cx = p[0]; cy = p[1]; w = p[2]; h = p[3];
        c = rc[k];
    }
    c = fminf(fmaxf(c, 0.0f), 1.0f);
    float hw = __fmul_rn(w, 0.5f);
    float hh = __fmul_rn(h, 0.5f);
    u_x1[i] = __fsub_rn(cx, hw);
    u_y1[i] = __fsub_rn(cy, hh);
    u_x2[i] = __fadd_rn(cx, hw);
    u_y2[i] = __fadd_rn(cy, hh);
    u_conf[i] = c;
    // descending conf, ties -> ascending original index (stable argsort semantics)
    u_key[i] = ((unsigned long long)__float_as_uint(c) << 32)
             | (unsigned long long)(0xFFFFFFFFu - (unsigned)i);
    g_rank[i] = 0;
}

// ---------------- K2: rank = #{j : key[j] > key[i]} (split over j-chunks) ----------------
#define CHUNK 2176
__global__ void k_rank() {
    __shared__ unsigned long long sk[CHUNK];
    int jbase = blockIdx.y * CHUNK;
    for (int t = threadIdx.x; t < CHUNK; t += blockDim.x) {
        int j = jbase + t;
        sk[t] = (j < N_TOTAL) ? u_key[j] : 0ull;   // 0 never beats a real key
    }
    __syncthreads();
    int i = blockIdx.x * blockDim.x + threadIdx.x;
    if (i >= N_TOTAL) return;
    unsigned long long ki = u_key[i];
    int c0 = 0, c1 = 0;
#pragma unroll 16
    for (int t = 0; t < CHUNK; t += 2) {
        c0 += (sk[t]     > ki) ? 1 : 0;
        c1 += (sk[t + 1] > ki) ? 1 : 0;
    }
    atomicAdd(&g_rank[i], c0 + c1);
}

// ---------------- K3: scatter into sorted order ----------------
__global__ void k_scatter() {
    int i = blockIdx.x * blockDim.x + threadIdx.x;
    if (i >= N_TOTAL) return;
    int r = g_rank[i];
    s_x1[r] = u_x1[i]; s_y1[r] = u_y1[i];
    s_x2[r] = u_x2[i]; s_y2[r] = u_y2[i];
    s_conf[r] = u_conf[i];
}

// ---------------- K4: sparse suppression build (i suppresses j>i with iou>0.5) ----------------
// 2 i-rows per thread: each shared J load is amortized over two IoU evals.
#define IT 64   // i rows per block (32 lanes x 2)
#define WT 8    // words per block (8*64 = 512 j's)
__global__ void k_mask() {
    __shared__ float4 jb[WT * 64];
    __shared__ float  ja[WT * 64];
    int i0 = blockIdx.x * IT;                 // 64-aligned => igroup = blockIdx.x for all i
    int w0 = blockIdx.y * WT;
    int jb0 = w0 * 64;
    if (jb0 + WT * 64 <= i0) return;          // block fully below diagonal
    for (int t = threadIdx.x; t < WT * 64; t += blockDim.x) {
        int j = jb0 + t;                      // j <= 8703 < N_PAD always
        float4 J = make_float4(s_x1[j], s_y1[j], s_x2[j], s_y2[j]);
        jb[t] = J;
        ja[t] = __fmul_rn(__fsub_rn(J.z, J.x), __fsub_rn(J.w, J.y));
    }
    __syncthreads();
    int il = threadIdx.x & 31;
    int wl = threadIdx.x >> 5;
    int igroup = blockIdx.x;
    int word = w0 + wl;
    if (word < igroup) return;                // all j <= i for this warp's word
    int i1 = i0 + il;                         // < 8672 < N_TOTAL always
    int i2 = i1 + 32;                         // may be pad (zero box -> bits stay 0)
    float ax1 = s_x1[i1], ay1 = s_y1[i1], ax2 = s_x2[i1], ay2 = s_y2[i1];
    float bx1 = s_x1[i2], by1 = s_y1[i2], bx2 = s_x2[i2], by2 = s_y2[i2];
    float aa = __fmul_rn(__fsub_rn(ax2, ax1), __fsub_rn(ay2, ay1));
    float ab = __fmul_rn(__fsub_rn(bx2, bx1), __fsub_rn(by2, by1));
    unsigned long long bits1 = 0ull, bits2 = 0ull;
    int tb = wl * 64;
#pragma unroll 8
    for (int b = 0; b < 64; b++) {
        float4 J = jb[tb + b];
        float aj = ja[tb + b];
        // pair (i1, j)
        float iw1 = fmaxf(__fsub_rn(fminf(ax2, J.z), fmaxf(ax1, J.x)), 0.0f);
        float ih1 = fmaxf(__fsub_rn(fminf(ay2, J.w), fmaxf(ay1, J.y)), 0.0f);
        float in1 = __fmul_rn(iw1, ih1);
        float un1 = __fsub_rn(__fadd_rn(aa, aj), in1);
        if (in1 > __fmul_rn(0.49f, un1)) {    // safe pre-filter (guarantees iou<0.5 if false)
            if (__fdiv_rn(in1, fmaxf(un1, 1e-9f)) > 0.5f) bits1 |= (1ull << b);
        }
        // pair (i2, j)
        float iw2 = fmaxf(__fsub_rn(fminf(bx2, J.z), fmaxf(bx1, J.x)), 0.0f);
        float ih2 = fmaxf(__fsub_rn(fminf(by2, J.w), fmaxf(by1, J.y)), 0.0f);
        float in2 = __fmul_rn(iw2, ih2);
        float un2 = __fsub_rn(__fadd_rn(ab, aj), in2);
        if (in2 > __fmul_rn(0.49f, un2)) {
            if (__fdiv_rn(in2, fmaxf(un2, 1e-9f)) > 0.5f) bits2 |= (1ull << b);
        }
    }
    if (word == igroup) {                     // straddling word -> diag entries
        int d1 = il;                          // i1 - jbase
        int d2 = il + 32;                     // i2 - jbase
        bits1 &= (~0ull << (d1 + 1));         // d1 <= 31
        bits2 = (d2 >= 63) ? 0ull : (bits2 & (~0ull << (d2 + 1)));
        g_diag[i1] = bits1;
        g_diag[i2] = bits2;
        unsigned long long hd = (bits1 ? (1ull << d1) : 0ull)
                              | (bits2 ? (1ull << d2) : 0ull);
        if (hd) atomicOr(&g_hasdiag[igroup], hd);
    } else {                                  // word > igroup: sparse off-diagonal entries
        if (bits1) {
            int pos = atomicAdd(&col_count[word], 1);
            if (pos < CAP) col_ent[word][pos] = make_ulonglong2((unsigned long long)i1, bits1);
        }
        if (bits2) {
            int pos = atomicAdd(&col_count[word], 1);
            if (pos < CAP) col_ent[word][pos] = make_ulonglong2((unsigned long long)i2, bits2);
        }
    }
}

// ---------------- K5: sparse scan with distance-2 register prefetch ----------------
__global__ void k_scan() {
    __shared__ unsigned long long keep[N_WORDS];
    __shared__ unsigned long long hds[N_WORDS];
    __shared__ unsigned long long remv_out[N_WORDS];
    __shared__ int scnt[N_WORDS];
    __shared__ unsigned long long s_part[8];
    int tid = threadIdx.x;
    int wid = tid >> 5, lane = tid & 31;
    if (tid < N_WORDS) {
        hds[tid] = g_hasdiag[tid];
        int c = col_count[tid];
        scnt[tid] = (c > CAP) ? CAP : c;
    }
    __syncthreads();

    // register-resident entry sets for groups g (parity) and g+1
    ulonglong2 eA[MPT], eB[MPT];
    {
        int cA = scnt[0];
#pragma unroll
        for (int m = 0; m < MPT; m++) {
            int k = tid + (m << 8);
            eA[m] = (k < cA) ? col_ent[0][k] : make_ulonglong2(0ull, 0ull);
        }
        int cB = scnt[1];
#pragma unroll
        for (int m = 0; m < MPT; m++) {
            int k = tid + (m << 8);
            eB[m] = (k < cB) ? col_ent[1][k] : make_ulonglong2(0ull, 0ull);
        }
    }

    for (int g = 0; g < N_WORDS; g++) {
        unsigned long long valid = (g == N_WORDS - 1) ? ((1ull << LAST_BITS) - 1ull)
                                                      : ~0ull;
        // t0: speculatively preload up to 4 in-group diag words
        unsigned long long pre_d0 = 0, pre_d1 = 0, pre_d2 = 0, pre_d3 = 0;
        int pre_b0 = -1, pre_b1 = -1, pre_b2 = -1, pre_b3 = -1;
        unsigned long long hd = 0ull;
        if (tid == 0) {
            hd = hds[g] & valid;
            unsigned long long t = hd;
            if (t) { pre_b0 = __ffsll(t) - 1; t &= t - 1; pre_d0 = g_diag[g * 64 + pre_b0]; }
            if (t) { pre_b1 = __ffsll(t) - 1; t &= t - 1; pre_d1 = g_diag[g * 64 + pre_b1]; }
            if (t) { pre_b2 = __ffsll(t) - 1; t &= t - 1; pre_d2 = g_diag[g * 64 + pre_b2]; }
            if (t) { pre_b3 = __ffsll(t) - 1;             pre_d3 = g_diag[g * 64 + pre_b3]; }
        }
        // phase 1: OR keep-gated entries (registers; zero-sentinel entries are no-ops)
        int cnt = scnt[g];
        unsigned long long part = 0ull;
        if (g & 1) {
#pragma unroll
            for (int m = 0; m < MPT; m++) {
                int i = (int)eB[m].x;
                if ((keep[i >> 6] >> (i & 63)) & 1ull) part |= eB[m].y;
            }
        } else {
#pragma unroll
            for (int m = 0; m < MPT; m++) {
                int i = (int)eA[m].x;
                if ((keep[i >> 6] >> (i & 63)) & 1ull) part |= eA[m].y;
            }
        }
        for (int k = (MPT << 8) + tid; k < cnt; k += 256) {   // overflow fallback (rare)
            ulonglong2 e = col_ent[g][k];
            int i = (int)e.x;
            if ((keep[i >> 6] >> (i & 63)) & 1ull) part |= e.y;
        }
        unsigned lo = __reduce_or_sync(0xFFFFFFFFu, (unsigned)part);
        unsigned hi = __reduce_or_sync(0xFFFFFFFFu, (unsigned)(part >> 32));
        if (lane == 0) s_part[wid] = ((unsigned long long)hi << 32) | lo;
        // prefetch group g+2 into the set just consumed
        int g2 = g + 2;
        if (g2 < N_WORDS) {
            int c2 = scnt[g2];
            if (g & 1) {
#pragma unroll
                for (int m = 0; m < MPT; m++) {
                    int k = tid + (m << 8);
                    eB[m] = (k < c2) ? col_ent[g2][k] : make_ulonglong2(0ull, 0ull);
                }
            } else {
#pragma unroll
                for (int m = 0; m < MPT; m++) {
                    int k = tid + (m << 8);
                    eA[m] = (k < c2) ? col_ent[g2][k] : make_ulonglong2(0ull, 0ull);
                }
            }
        }
        __syncthreads();
        // phase 2: t0 combines warp partials + resolves rare in-group chain
        if (tid == 0) {
            unsigned long long removed = 0ull;
#pragma unroll
            for (int w = 0; w < 8; w++) removed |= s_part[w];
            unsigned long long m = hd & ~removed;
            while (m) {
                int b = __ffsll(m) - 1;
                if (!((removed >> b) & 1ull)) {
                    unsigned long long d;
                    if      (b == pre_b0) d = pre_d0;
                    else if (b == pre_b1) d = pre_d1;
                    else if (b == pre_b2) d = pre_d2;
                    else if (b == pre_b3) d = pre_d3;
                    else                  d = g_diag[g * 64 + b];
                    removed |= d;
                }
                m &= m - 1;
                m &= ~removed;
            }
            keep[g] = valid & ~removed;
            remv_out[g] = removed;
        }
        __syncthreads();
    }
    if (tid < N_WORDS) g_remv[tid] = remv_out[tid];
}

// ---------------- K6: write (x1,y1,x2,y2,conf) * keep ----------------
__global__ void k_out(float* __restrict__ out) {
    int r = blockIdx.x * blockDim.x + threadIdx.x;
    if (r >= N_TOTAL) return;
    bool keep = !((g_remv[r >> 6] >> (r & 63)) & 1ull);
    float m = keep ? 1.0f : 0.0f;
    out[r * 5 + 0] = __fmul_rn(s_x1[r], m);
    out[r * 5 + 1] = __fmul_rn(s_y1[r], m);
    out[r * 5 + 2] = __fmul_rn(s_x2[r], m);
    out[r * 5 + 3] = __fmul_rn(s_y2[r], m);
    out[r * 5 + 4] = __fmul_rn(s_conf[r], m);
}

// ---------------- launch ----------------
extern "C" void kernel_launch(void* const* d_in, const int* in_sizes, int n_in,
                              void* d_out, int out_size) {
    const float* yb = (const float*)d_in[0];   // yolo_cxcywh   [8400,4]
    const float* yc = (const float*)d_in[1];   // yolo_conf     [8400]
    const float* rb = (const float*)d_in[2];   // rtdetr_cxcywh [300,4]
    const float* rc = (const float*)d_in[3];   // rtdetr_conf   [300]
    float* out = (float*)d_out;

    const int TB = 256;
    const int NB = (N_TOTAL + TB - 1) / TB;    // 34

    k_prep<<<NB, TB>>>(yb, yc, rb, rc);
    k_rank<<<dim3(NB, (N_TOTAL + CHUNK - 1) / CHUNK), TB>>>();
    k_scatter<<<NB, TB>>>();
    k_mask<<<dim3(N_PAD / IT, N_WORDS / WT), 256>>>();
    k_scan<<<1, 256>>>();
    k_out<<<NB, TB>>>(out);
}